// round 16
// baseline (speedup 1.0000x reference)
#include <cuda_runtime.h>

#define EPSV   1e-5f
#define DW_THR 4.0f
#define PW_THR 0.001f

// Shapes: B=64, C=128, O=256, H=W=56, HW=3136
__device__ float g_y[64 * 128 * 3136];   // pruned depthwise output [B,C,HW]
__device__ int   g_keep[64 * 128];       // per-(b,c) keep flag
__device__ int   g_idx[64 * 128];        // per-b compacted kept-channel list
__device__ int   g_cnt[64];              // per-b kept count

// ---------------------------------------------------------------------------
// packed fp32x2 helpers (Blackwell FFMA2)
// ---------------------------------------------------------------------------
__device__ __forceinline__ unsigned long long fma2(unsigned long long a,
                                                   unsigned long long b,
                                                   unsigned long long c) {
    unsigned long long d;
    asm("fma.rn.f32x2 %0, %1, %2, %3;" : "=l"(d) : "l"(a), "l"(b), "l"(c));
    return d;
}
__device__ __forceinline__ unsigned long long mul2(unsigned long long a,
                                                   unsigned long long b) {
    unsigned long long d;
    asm("mul.rn.f32x2 %0, %1, %2;" : "=l"(d) : "l"(a), "l"(b));
    return d;
}
__device__ __forceinline__ unsigned long long pk2(float lo, float hi) {
    unsigned long long d;
    asm("mov.b64 %0, {%1, %2};" : "=l"(d) : "f"(lo), "f"(hi));
    return d;
}
__device__ __forceinline__ float2 upk2(unsigned long long v) {
    float2 r;
    asm("mov.b64 {%0, %1}, %2;" : "=f"(r.x), "=f"(r.y) : "l"(v));
    return r;
}

// ---------------------------------------------------------------------------
// Depthwise 3x3 + bias + BN1 + ReLU + per-(b,c) prune.
// (round-12/15 version, measured ~38us, occ ~93% — do not touch)
// ---------------------------------------------------------------------------
__global__ __launch_bounds__(256) void dw_kernel(
    const float* __restrict__ x,
    const float* __restrict__ dw_w, const float* __restrict__ dw_b,
    const float* __restrict__ g1,  const float* __restrict__ b1,
    const float* __restrict__ m1,  const float* __restrict__ v1)
{
    __shared__ float sx[3136];
    __shared__ float red[8];
    __shared__ float s_bmax;

    const int slice = blockIdx.x;          // b*128 + c
    const int c = slice & 127;
    const float* xs = x + (size_t)slice * 3136;

    const unsigned long long ww0 = pk2(dw_w[c*9+0], dw_w[c*9+0]);
    const unsigned long long ww1 = pk2(dw_w[c*9+1], dw_w[c*9+1]);
    const unsigned long long ww2 = pk2(dw_w[c*9+2], dw_w[c*9+2]);
    const unsigned long long ww3 = pk2(dw_w[c*9+3], dw_w[c*9+3]);
    const unsigned long long ww4 = pk2(dw_w[c*9+4], dw_w[c*9+4]);
    const unsigned long long ww5 = pk2(dw_w[c*9+5], dw_w[c*9+5]);
    const unsigned long long ww6 = pk2(dw_w[c*9+6], dw_w[c*9+6]);
    const unsigned long long ww7 = pk2(dw_w[c*9+7], dw_w[c*9+7]);
    const unsigned long long ww8 = pk2(dw_w[c*9+8], dw_w[c*9+8]);
    const float s = g1[c] * rsqrtf(v1[c] + EPSV);
    const float t = fmaf(dw_b[c] - m1[c], s, b1[c]);
    const unsigned long long ss = pk2(s, s);
    const unsigned long long tt = pk2(t, t);

    const int tid = threadIdx.x;

    {   // stage slice: 784 coalesced float4
        const float4* x4 = (const float4*)xs;
        float4* s4 = (float4*)sx;
        for (int i = tid; i < 784; i += 256) s4[i] = x4[i];
    }
    __syncthreads();

    float2 lv[7];
    float mx = 0.f;
    int p = 0, band = 0;
    if (tid < 224) {
        band = tid / 28;               // 0..7
        p    = tid - band * 28;        // col pair -> cols 2p, 2p+1
        const bool cL = (p > 0), cR = (p < 27);
        const int col = 2 * p;
        const int r0  = band * 7;

        unsigned long long r0q0, r0q1, r0q2, r1q0, r1q1, r1q2;
        {
            float c0 = 0.f, c1 = 0.f, c2 = 0.f, c3 = 0.f;
            if (r0 > 0) {
                int a = (r0 - 1) * 56 + col;
                c0 = cL ? sx[a - 1] : 0.f;
                c1 = sx[a]; c2 = sx[a + 1];
                c3 = cR ? sx[a + 2] : 0.f;
            }
            r0q0 = pk2(c0, c1); r0q1 = pk2(c1, c2); r0q2 = pk2(c2, c3);
        }
        {
            int a = r0 * 56 + col;
            float c0 = cL ? sx[a - 1] : 0.f;
            float c1 = sx[a], c2 = sx[a + 1];
            float c3 = cR ? sx[a + 2] : 0.f;
            r1q0 = pk2(c0, c1); r1q1 = pk2(c1, c2); r1q2 = pk2(c2, c3);
        }

#pragma unroll
        for (int j = 0; j < 7; j++) {
            const int rr = r0 + j + 1;
            unsigned long long r2q0, r2q1, r2q2;
            {
                float c0 = 0.f, c1 = 0.f, c2 = 0.f, c3 = 0.f;
                if (rr < 56) {
                    int a = rr * 56 + col;
                    c0 = cL ? sx[a - 1] : 0.f;
                    c1 = sx[a]; c2 = sx[a + 1];
                    c3 = cR ? sx[a + 2] : 0.f;
                }
                r2q0 = pk2(c0, c1); r2q1 = pk2(c1, c2); r2q2 = pk2(c2, c3);
            }
            unsigned long long acc = mul2(r0q0, ww0);
            acc = fma2(r0q1, ww1, acc); acc = fma2(r0q2, ww2, acc);
            acc = fma2(r1q0, ww3, acc); acc = fma2(r1q1, ww4, acc);
            acc = fma2(r1q2, ww5, acc);
            acc = fma2(r2q0, ww6, acc); acc = fma2(r2q1, ww7, acc);
            acc = fma2(r2q2, ww8, acc);
            acc = fma2(acc, ss, tt);
            float2 pr = upk2(acc);
            float z0 = fmaxf(pr.x, 0.f), z1 = fmaxf(pr.y, 0.f);
            lv[j] = make_float2(z0, z1);
            mx = fmaxf(mx, fmaxf(z0, z1));
            r0q0 = r1q0; r0q1 = r1q1; r0q2 = r1q2;
            r1q0 = r2q0; r1q1 = r2q1; r1q2 = r2q2;
        }
    }

    for (int off = 16; off; off >>= 1)
        mx = fmaxf(mx, __shfl_xor_sync(0xffffffffu, mx, off));
    if ((tid & 31) == 0) red[tid >> 5] = mx;
    __syncthreads();
    if (tid == 0) {
        float m = red[0];
#pragma unroll
        for (int i = 1; i < 8; i++) m = fmaxf(m, red[i]);
        s_bmax = m;
        g_keep[slice] = (m >= DW_THR) ? 1 : 0;
    }
    __syncthreads();

    if (s_bmax >= DW_THR && tid < 224) {
        float* yo = g_y + (size_t)slice * 3136 + band * 7 * 56 + 2 * p;
#pragma unroll
        for (int j = 0; j < 7; j++)
            *(float2*)(yo + j * 56) = lv[j];
    }
}

// ---------------------------------------------------------------------------
// Per-batch compaction of kept channels
// ---------------------------------------------------------------------------
__global__ void compact_kernel() {
    const int b = blockIdx.x;
    const int tid = threadIdx.x;              // 128 threads
    __shared__ int wcnt[4];
    const int f = g_keep[b * 128 + tid];
    const unsigned bal = __ballot_sync(0xffffffffu, f);
    const int lane = tid & 31, w = tid >> 5;
    const int pre = __popc(bal & ((1u << lane) - 1u));
    if (lane == 0) wcnt[w] = __popc(bal);
    __syncthreads();
    int off = 0;
#pragma unroll
    for (int i = 0; i < 4; i++) if (i < w) off += wcnt[i];
    if (f) g_idx[b * 128 + off + pre] = tid;
    if (tid == 0) g_cnt[b] = wcnt[0] + wcnt[1] + wcnt[2] + wcnt[3];
}

// ---------------------------------------------------------------------------
// Pointwise conv + BN2 + ReLU + BLOCK-LOCAL prune — BARRIER-FREE mainloop.
// Block = 32 O x 3136 HW stripe. grid (8, 64) = 512 blocks, 256 threads.
// W staged once (duplicated pairs) + per-k Y row pointers; ONE sync total.
// Y read directly via coalesced LDG.128 (L1/L2-hot; Y is L2-resident).
// Thread = 4 o's (warp ty) x 8 hw (lane tx*8): per k = 1 LDS.64 + 2 LDG.128
// + 2 LDS.128 + 16 fma2. Unified path for any cnt (sWd holds all 128 k).
// ---------------------------------------------------------------------------
__global__ __launch_bounds__(256, 3) void pw_kernel(
    const float* __restrict__ pw_w, const float* __restrict__ pw_b,
    const float* __restrict__ g2,  const float* __restrict__ b2,
    const float* __restrict__ m2,  const float* __restrict__ v2,
    float* __restrict__ out)
{
    __shared__ __align__(16) float sWd[128][72];      // [k][2*o] duplicated W
    __shared__ const float* sptr[128];                // per-k g_y row pointer
    __shared__ unsigned char sfail[32];

    const int tid = threadIdx.x;
    const int tx = tid & 31;                 // hw: 32 lanes x 8 floats
    const int ty = tid >> 5;                 // o : 8 warps x 4 o's
    const int ob = blockIdx.x * 32;
    const int b  = blockIdx.y;

    const int cnt  = g_cnt[b];
    const int cnt4 = (cnt + 3) & ~3;         // padded rows: W=0, dummy ptr

    // per-k row pointers (dummy = batch's channel-0 row; W=0 kills it exactly)
    if (tid < 128) {
        const float* base = g_y + ((size_t)b * 128) * 3136;
        if (tid < cnt) base = g_y + ((size_t)(b * 128 + g_idx[b * 128 + tid])) * 3136;
        sptr[tid] = base;
    }
    // stage W once, duplicated (reads g_idx directly; L2-hot)
    for (int i = tid; i < cnt4 * 32; i += 256) {
        int lk = i >> 5, oo = i & 31;
        float w = 0.f;
        if (lk < cnt) w = pw_w[(ob + oo) * 128 + g_idx[b * 128 + lk]];
        sWd[lk][2 * oo]     = w;
        sWd[lk][2 * oo + 1] = w;
    }
    __syncthreads();                          // the ONLY block-wide sync (until prune)

    float sc[4], tc[4], m[4];
#pragma unroll
    for (int r = 0; r < 4; r++) {
        int o = ob + ty * 4 + r;
        sc[r] = g2[o] * rsqrtf(v2[o] + EPSV);
        tc[r] = fmaf(pw_b[o] - m2[o], sc[r], b2[o]);
        m[r] = 0.f;
    }
    const size_t outbase = ((size_t)(b * 256 + ob + ty * 4)) * 3136;

    // 13 iterations of 256-hw; it=12 is the 64-wide tail (tx<8 live)
    for (int it = 0; it < 13; it++) {
        const int hw = it * 256 + tx * 8;
        if (hw >= 3136) break;                 // uniform per warp except tail warp

        unsigned long long acc[4][4];          // [o][hw-pair]
#pragma unroll
        for (int r = 0; r < 4; r++)
#pragma unroll
            for (int q = 0; q < 4; q++) acc[r][q] = 0ull;

        for (int k0 = 0; k0 < cnt4; k0 += 4) {
#pragma unroll
            for (int ku = 0; ku < 4; ku++) {
                const int k = k0 + ku;
                const float* yp = sptr[k];
                ulonglong2 Ya = *(const ulonglong2*)(yp + hw);      // pairs 0,1
                ulonglong2 Yb = *(const ulonglong2*)(yp + hw + 4);  // pairs 2,3
                ulonglong2 W01 = *(const ulonglong2*)&sWd[k][ty * 8];
                ulonglong2 W23 = *(const ulonglong2*)&sWd[k][ty * 8 + 4];
                acc[0][0] = fma2(W01.x, Ya.x, acc[0][0]);
                acc[0][1] = fma2(W01.x, Ya.y, acc[0][1]);
                acc[0][2] = fma2(W01.x, Yb.x, acc[0][2]);
                acc[0][3] = fma2(W01.x, Yb.y, acc[0][3]);
                acc[1][0] = fma2(W01.y, Ya.x, acc[1][0]);
                acc[1][1] = fma2(W01.y, Ya.y, acc[1][1]);
                acc[1][2] = fma2(W01.y, Yb.x, acc[1][2]);
                acc[1][3] = fma2(W01.y, Yb.y, acc[1][3]);
                acc[2][0] = fma2(W23.x, Ya.x, acc[2][0]);
                acc[2][1] = fma2(W23.x, Ya.y, acc[2][1]);
                acc[2][2] = fma2(W23.x, Yb.x, acc[2][2]);
                acc[2][3] = fma2(W23.x, Yb.y, acc[2][3]);
                acc[3][0] = fma2(W23.y, Ya.x, acc[3][0]);
                acc[3][1] = fma2(W23.y, Ya.y, acc[3][1]);
                acc[3][2] = fma2(W23.y, Yb.x, acc[3][2]);
                acc[3][3] = fma2(W23.y, Yb.y, acc[3][3]);
            }
        }

        // epilogue: BN2 + ReLU + max + 2x STG.128 per o
#pragma unroll
        for (int r = 0; r < 4; r++) {
            float2 a0 = upk2(acc[r][0]);
            float2 a1 = upk2(acc[r][1]);
            float2 a2 = upk2(acc[r][2]);
            float2 a3 = upk2(acc[r][3]);
            float z0 = fmaxf(fmaf(a0.x, sc[r], tc[r]), 0.f);
            float z1 = fmaxf(fmaf(a0.y, sc[r], tc[r]), 0.f);
            float z2 = fmaxf(fmaf(a1.x, sc[r], tc[r]), 0.f);
            float z3 = fmaxf(fmaf(a1.y, sc[r], tc[r]), 0.f);
            float z4 = fmaxf(fmaf(a2.x, sc[r], tc[r]), 0.f);
            float z5 = fmaxf(fmaf(a2.y, sc[r], tc[r]), 0.f);
            float z6 = fmaxf(fmaf(a3.x, sc[r], tc[r]), 0.f);
            float z7 = fmaxf(fmaf(a3.y, sc[r], tc[r]), 0.f);
            m[r] = fmaxf(m[r], fmaxf(fmaxf(fmaxf(z0, z1), fmaxf(z2, z3)),
                                     fmaxf(fmaxf(z4, z5), fmaxf(z6, z7))));
            float* po = out + outbase + (size_t)r * 3136 + hw;
            *(float4*)po       = make_float4(z0, z1, z2, z3);
            *(float4*)(po + 4) = make_float4(z4, z5, z6, z7);
        }
    }

    // per-o max over 32 lanes
#pragma unroll
    for (int r = 0; r < 4; r++) {
#pragma unroll
        for (int off = 1; off < 32; off <<= 1)
            m[r] = fmaxf(m[r], __shfl_xor_sync(0xffffffffu, m[r], off));
    }
    if (tx == 0) {
#pragma unroll
        for (int r = 0; r < 4; r++)
            sfail[ty * 4 + r] = (m[r] < PW_THR) ? 1 : 0;
    }
    __syncthreads();

    // block-local prune: zero failing rows
    const float4 zz = make_float4(0.f, 0.f, 0.f, 0.f);
    for (int oo = 0; oo < 32; oo++) {
        if (sfail[oo]) {
            float4* p4 = (float4*)(out + ((size_t)(b * 256 + ob + oo)) * 3136);
            for (int i = tid; i < 784; i += 256) p4[i] = zz;
        }
    }
}

// ---------------------------------------------------------------------------
extern "C" void kernel_launch(void* const* d_in, const int* in_sizes, int n_in,
                              void* d_out, int out_size)
{
    const float* x    = (const float*)d_in[0];
    const float* dw_w = (const float*)d_in[1];
    const float* dw_b = (const float*)d_in[2];
    const float* g1   = (const float*)d_in[3];
    const float* b1   = (const float*)d_in[4];
    const float* m1   = (const float*)d_in[5];
    const float* v1   = (const float*)d_in[6];
    const float* pw_w = (const float*)d_in[7];
    const float* pw_b = (const float*)d_in[8];
    const float* g2   = (const float*)d_in[9];
    const float* b2   = (const float*)d_in[10];
    const float* m2   = (const float*)d_in[11];
    const float* v2   = (const float*)d_in[12];
    float* out = (float*)d_out;

    dw_kernel<<<64 * 128, 256>>>(x, dw_w, dw_b, g1, b1, m1, v1);
    compact_kernel<<<64, 128>>>();
    pw_kernel<<<dim3(8, 64), 256>>>(pw_w, pw_b, g2, b2, m2, v2, out);
}

// round 17
// speedup vs baseline: 1.1046x; 1.1046x over previous
#include <cuda_runtime.h>

#define EPSV   1e-5f
#define DW_THR 4.0f
#define PW_THR 0.001f

// Shapes: B=64, C=128, O=256, H=W=56, HW=3136
__device__ float g_y[64 * 128 * 3136];   // pruned depthwise output [B,C,HW]
__device__ int   g_keep[64 * 128];       // per-(b,c) keep flag
__device__ int   g_idx[64 * 128];        // per-b compacted kept-channel list
__device__ int   g_cnt[64];              // per-b kept count

// ---------------------------------------------------------------------------
// packed fp32x2 helpers (Blackwell FFMA2)
// ---------------------------------------------------------------------------
__device__ __forceinline__ unsigned long long fma2(unsigned long long a,
                                                   unsigned long long b,
                                                   unsigned long long c) {
    unsigned long long d;
    asm("fma.rn.f32x2 %0, %1, %2, %3;" : "=l"(d) : "l"(a), "l"(b), "l"(c));
    return d;
}
__device__ __forceinline__ unsigned long long mul2(unsigned long long a,
                                                   unsigned long long b) {
    unsigned long long d;
    asm("mul.rn.f32x2 %0, %1, %2;" : "=l"(d) : "l"(a), "l"(b));
    return d;
}
__device__ __forceinline__ unsigned long long pk2(float lo, float hi) {
    unsigned long long d;
    asm("mov.b64 %0, {%1, %2};" : "=l"(d) : "f"(lo), "f"(hi));
    return d;
}
__device__ __forceinline__ float2 upk2(unsigned long long v) {
    float2 r;
    asm("mov.b64 {%0, %1}, %2;" : "=f"(r.x), "=f"(r.y) : "l"(v));
    return r;
}

// ---------------------------------------------------------------------------
// Depthwise 3x3 + bias + BN1 + ReLU + per-(b,c) prune. (passing, ~38us)
// ---------------------------------------------------------------------------
__global__ __launch_bounds__(256) void dw_kernel(
    const float* __restrict__ x,
    const float* __restrict__ dw_w, const float* __restrict__ dw_b,
    const float* __restrict__ g1,  const float* __restrict__ b1,
    const float* __restrict__ m1,  const float* __restrict__ v1)
{
    __shared__ float sx[3136];
    __shared__ float red[8];
    __shared__ float s_bmax;

    const int slice = blockIdx.x;          // b*128 + c
    const int c = slice & 127;
    const float* xs = x + (size_t)slice * 3136;

    const unsigned long long ww0 = pk2(dw_w[c*9+0], dw_w[c*9+0]);
    const unsigned long long ww1 = pk2(dw_w[c*9+1], dw_w[c*9+1]);
    const unsigned long long ww2 = pk2(dw_w[c*9+2], dw_w[c*9+2]);
    const unsigned long long ww3 = pk2(dw_w[c*9+3], dw_w[c*9+3]);
    const unsigned long long ww4 = pk2(dw_w[c*9+4], dw_w[c*9+4]);
    const unsigned long long ww5 = pk2(dw_w[c*9+5], dw_w[c*9+5]);
    const unsigned long long ww6 = pk2(dw_w[c*9+6], dw_w[c*9+6]);
    const unsigned long long ww7 = pk2(dw_w[c*9+7], dw_w[c*9+7]);
    const unsigned long long ww8 = pk2(dw_w[c*9+8], dw_w[c*9+8]);
    const float s = g1[c] * rsqrtf(v1[c] + EPSV);
    const float t = fmaf(dw_b[c] - m1[c], s, b1[c]);
    const unsigned long long ss = pk2(s, s);
    const unsigned long long tt = pk2(t, t);

    const int tid = threadIdx.x;

    {   // stage slice: 784 coalesced float4
        const float4* x4 = (const float4*)xs;
        float4* s4 = (float4*)sx;
        for (int i = tid; i < 784; i += 256) s4[i] = x4[i];
    }
    __syncthreads();

    float2 lv[7];
    float mx = 0.f;
    int p = 0, band = 0;
    if (tid < 224) {
        band = tid / 28;               // 0..7
        p    = tid - band * 28;        // col pair -> cols 2p, 2p+1
        const bool cL = (p > 0), cR = (p < 27);
        const int col = 2 * p;
        const int r0  = band * 7;

        unsigned long long r0q0, r0q1, r0q2, r1q0, r1q1, r1q2;
        {
            float c0 = 0.f, c1 = 0.f, c2 = 0.f, c3 = 0.f;
            if (r0 > 0) {
                int a = (r0 - 1) * 56 + col;
                c0 = cL ? sx[a - 1] : 0.f;
                c1 = sx[a]; c2 = sx[a + 1];
                c3 = cR ? sx[a + 2] : 0.f;
            }
            r0q0 = pk2(c0, c1); r0q1 = pk2(c1, c2); r0q2 = pk2(c2, c3);
        }
        {
            int a = r0 * 56 + col;
            float c0 = cL ? sx[a - 1] : 0.f;
            float c1 = sx[a], c2 = sx[a + 1];
            float c3 = cR ? sx[a + 2] : 0.f;
            r1q0 = pk2(c0, c1); r1q1 = pk2(c1, c2); r1q2 = pk2(c2, c3);
        }

#pragma unroll
        for (int j = 0; j < 7; j++) {
            const int rr = r0 + j + 1;
            unsigned long long r2q0, r2q1, r2q2;
            {
                float c0 = 0.f, c1 = 0.f, c2 = 0.f, c3 = 0.f;
                if (rr < 56) {
                    int a = rr * 56 + col;
                    c0 = cL ? sx[a - 1] : 0.f;
                    c1 = sx[a]; c2 = sx[a + 1];
                    c3 = cR ? sx[a + 2] : 0.f;
                }
                r2q0 = pk2(c0, c1); r2q1 = pk2(c1, c2); r2q2 = pk2(c2, c3);
            }
            unsigned long long acc = mul2(r0q0, ww0);
            acc = fma2(r0q1, ww1, acc); acc = fma2(r0q2, ww2, acc);
            acc = fma2(r1q0, ww3, acc); acc = fma2(r1q1, ww4, acc);
            acc = fma2(r1q2, ww5, acc);
            acc = fma2(r2q0, ww6, acc); acc = fma2(r2q1, ww7, acc);
            acc = fma2(r2q2, ww8, acc);
            acc = fma2(acc, ss, tt);
            float2 pr = upk2(acc);
            float z0 = fmaxf(pr.x, 0.f), z1 = fmaxf(pr.y, 0.f);
            lv[j] = make_float2(z0, z1);
            mx = fmaxf(mx, fmaxf(z0, z1));
            r0q0 = r1q0; r0q1 = r1q1; r0q2 = r1q2;
            r1q0 = r2q0; r1q1 = r2q1; r1q2 = r2q2;
        }
    }

    for (int off = 16; off; off >>= 1)
        mx = fmaxf(mx, __shfl_xor_sync(0xffffffffu, mx, off));
    if ((tid & 31) == 0) red[tid >> 5] = mx;
    __syncthreads();
    if (tid == 0) {
        float m = red[0];
#pragma unroll
        for (int i = 1; i < 8; i++) m = fmaxf(m, red[i]);
        s_bmax = m;
        g_keep[slice] = (m >= DW_THR) ? 1 : 0;
    }
    __syncthreads();

    if (s_bmax >= DW_THR && tid < 224) {
        float* yo = g_y + (size_t)slice * 3136 + band * 7 * 56 + 2 * p;
#pragma unroll
        for (int j = 0; j < 7; j++)
            *(float2*)(yo + j * 56) = lv[j];
    }
}

// ---------------------------------------------------------------------------
// Per-batch compaction of kept channels
// ---------------------------------------------------------------------------
__global__ void compact_kernel() {
    const int b = blockIdx.x;
    const int tid = threadIdx.x;              // 128 threads
    __shared__ int wcnt[4];
    const int f = g_keep[b * 128 + tid];
    const unsigned bal = __ballot_sync(0xffffffffu, f);
    const int lane = tid & 31, w = tid >> 5;
    const int pre = __popc(bal & ((1u << lane) - 1u));
    if (lane == 0) wcnt[w] = __popc(bal);
    __syncthreads();
    int off = 0;
#pragma unroll
    for (int i = 0; i < 4; i++) if (i < w) off += wcnt[i];
    if (f) g_idx[b * 128 + off + pre] = tid;
    if (tid == 0) g_cnt[b] = wcnt[0] + wcnt[1] + wcnt[2] + wcnt[3];
}

// ---------------------------------------------------------------------------
// Pointwise conv + BN2 + ReLU + BLOCK-LOCAL prune — crossbar-optimized.
// Block = 32 O x 3136 HW stripe. grid (8, 64) = 512 blocks, 256 threads.
// Microtile 8-o x 4-hw: per k per warp = 1 Y LDS.128 + 4 broadcast W loads
// feeding 16 fma2 (36 B/fma2 crossbar vs 68 before). Chunk = 256 hw; warps
// 0-3 cover hw[0:128), warps 4-7 cover hw[128:256); warp og = w&3 owns o's
// og*8..og*8+7. W staged ONCE for all cnt4 rows; Y single-buffered/chunk.
// ---------------------------------------------------------------------------
__global__ __launch_bounds__(256, 3) void pw_kernel(
    const float* __restrict__ pw_w, const float* __restrict__ pw_b,
    const float* __restrict__ g2,  const float* __restrict__ b2,
    const float* __restrict__ m2,  const float* __restrict__ v2,
    float* __restrict__ out)
{
    __shared__ __align__(16) float sWd[128][68];   // [k][2*oo] dup W, 272B rows
    __shared__ __align__(16) float sY[32][260];    // [k][256 hw + 4 pad]
    __shared__ int   sidx[128];
    __shared__ float swmax[8][8];
    __shared__ unsigned char sfail[32];

    const int tid  = threadIdx.x;
    const int lane = tid & 31;
    const int w    = tid >> 5;               // warp 0..7
    const int og   = w & 3;                  // o-group: o's og*8..og*8+7
    const int half = w >> 2;                 // hw half: 0 or 1
    const int ob   = blockIdx.x * 32;
    const int b    = blockIdx.y;

    const int cnt  = g_cnt[b];
    const int cnt4 = (cnt + 3) & ~3;
    const int nsub = (cnt4 + 31) >> 5;

    if (tid < 128) sidx[tid] = (tid < cnt) ? g_idx[b * 128 + tid] : -1;
    __syncthreads();

    // stage W once for ALL cnt4 rows, duplicated pairs
    for (int i = tid; i < cnt4 * 32; i += 256) {
        int lk = i >> 5, oo = i & 31;
        int ch = sidx[lk];
        float wv = (ch >= 0) ? pw_w[(ob + oo) * 128 + ch] : 0.f;
        sWd[lk][2 * oo]     = wv;
        sWd[lk][2 * oo + 1] = wv;
    }

    // BN constants for this warp's 8 o's
    float sc[8], tc[8], m[8];
#pragma unroll
    for (int r = 0; r < 8; r++) {
        int o = ob + og * 8 + r;
        sc[r] = g2[o] * rsqrtf(v2[o] + EPSV);
        tc[r] = fmaf(pw_b[o] - m2[o], sc[r], b2[o]);
        m[r] = 0.f;
    }
    const size_t outbase = ((size_t)(b * 256 + ob + og * 8)) * 3136;
    const int yoff = half * 128 + lane * 4;   // this thread's hw within chunk

    // 13 chunks of 256 hw (last = 64 wide)
    for (int it = 0; it < 13; it++) {
        const int hw0 = it * 256;
        const int whw = hw0 + yoff;
        const bool live = (whw < 3136);

        unsigned long long acc[8][2];
#pragma unroll
        for (int r = 0; r < 8; r++) { acc[r][0] = 0ull; acc[r][1] = 0ull; }

        for (int kt = 0; kt < nsub; kt++) {
            const int kbase = kt * 32;
            int klim = cnt4 - kbase;
            if (klim > 32) klim = 32;

            // stage Y chunk: klim x 64 f4 (256 hw)
            for (int i = tid; i < klim * 64; i += 256) {
                int lk = i >> 6, f4 = i & 63;
                int ch = sidx[kbase + lk];
                int hw = hw0 + f4 * 4;
                if (hw < 3136) {
                    float4 v = make_float4(0.f, 0.f, 0.f, 0.f);
                    if (ch >= 0)
                        v = *(const float4*)(g_y + ((size_t)(b * 128 + ch)) * 3136 + hw);
                    *(float4*)&sY[lk][f4 * 4] = v;
                }
            }
            __syncthreads();

            for (int lk0 = 0; lk0 < klim; lk0 += 4) {
#pragma unroll
                for (int ku = 0; ku < 4; ku++) {
                    const int lk = lk0 + ku;
                    const int gk = kbase + lk;
                    ulonglong2 Yp = *(const ulonglong2*)&sY[lk][yoff];
                    ulonglong2 W01 = *(const ulonglong2*)&sWd[gk][og * 16];
                    ulonglong2 W23 = *(const ulonglong2*)&sWd[gk][og * 16 + 4];
                    ulonglong2 W45 = *(const ulonglong2*)&sWd[gk][og * 16 + 8];
                    ulonglong2 W67 = *(const ulonglong2*)&sWd[gk][og * 16 + 12];
                    acc[0][0] = fma2(W01.x, Yp.x, acc[0][0]);
                    acc[0][1] = fma2(W01.x, Yp.y, acc[0][1]);
                    acc[1][0] = fma2(W01.y, Yp.x, acc[1][0]);
                    acc[1][1] = fma2(W01.y, Yp.y, acc[1][1]);
                    acc[2][0] = fma2(W23.x, Yp.x, acc[2][0]);
                    acc[2][1] = fma2(W23.x, Yp.y, acc[2][1]);
                    acc[3][0] = fma2(W23.y, Yp.x, acc[3][0]);
                    acc[3][1] = fma2(W23.y, Yp.y, acc[3][1]);
                    acc[4][0] = fma2(W45.x, Yp.x, acc[4][0]);
                    acc[4][1] = fma2(W45.x, Yp.y, acc[4][1]);
                    acc[5][0] = fma2(W45.y, Yp.x, acc[5][0]);
                    acc[5][1] = fma2(W45.y, Yp.y, acc[5][1]);
                    acc[6][0] = fma2(W67.x, Yp.x, acc[6][0]);
                    acc[6][1] = fma2(W67.x, Yp.y, acc[6][1]);
                    acc[7][0] = fma2(W67.y, Yp.x, acc[7][0]);
                    acc[7][1] = fma2(W67.y, Yp.y, acc[7][1]);
                }
            }
            __syncthreads();
        }

        if (live) {
#pragma unroll
            for (int r = 0; r < 8; r++) {
                float2 a0 = upk2(acc[r][0]);
                float2 a1 = upk2(acc[r][1]);
                float z0 = fmaxf(fmaf(a0.x, sc[r], tc[r]), 0.f);
                float z1 = fmaxf(fmaf(a0.y, sc[r], tc[r]), 0.f);
                float z2 = fmaxf(fmaf(a1.x, sc[r], tc[r]), 0.f);
                float z3 = fmaxf(fmaf(a1.y, sc[r], tc[r]), 0.f);
                m[r] = fmaxf(m[r], fmaxf(fmaxf(z0, z1), fmaxf(z2, z3)));
                *(float4*)(out + outbase + (size_t)r * 3136 + whw) =
                    make_float4(z0, z1, z2, z3);
            }
        }
    }

    // per-o max: reduce over lanes, then merge the two hw-half warps
#pragma unroll
    for (int r = 0; r < 8; r++) {
#pragma unroll
        for (int off = 1; off < 32; off <<= 1)
            m[r] = fmaxf(m[r], __shfl_xor_sync(0xffffffffu, m[r], off));
    }
    if (lane == 0) {
#pragma unroll
        for (int r = 0; r < 8; r++) swmax[w][r] = m[r];
    }
    __syncthreads();
    if (tid < 32) {
        int g = tid >> 3, r = tid & 7;        // oo = g*8 + r = tid
        float mm = fmaxf(swmax[g][r], swmax[g + 4][r]);
        sfail[tid] = (mm < PW_THR) ? 1 : 0;
    }
    __syncthreads();

    // block-local prune: zero failing rows
    const float4 zz = make_float4(0.f, 0.f, 0.f, 0.f);
    for (int oo = 0; oo < 32; oo++) {
        if (sfail[oo]) {
            float4* p4 = (float4*)(out + ((size_t)(b * 256 + ob + oo)) * 3136);
            for (int i = tid; i < 784; i += 256) p4[i] = zz;
        }
    }
}

// ---------------------------------------------------------------------------
extern "C" void kernel_launch(void* const* d_in, const int* in_sizes, int n_in,
                              void* d_out, int out_size)
{
    const float* x    = (const float*)d_in[0];
    const float* dw_w = (const float*)d_in[1];
    const float* dw_b = (const float*)d_in[2];
    const float* g1   = (const float*)d_in[3];
    const float* b1   = (const float*)d_in[4];
    const float* m1   = (const float*)d_in[5];
    const float* v1   = (const float*)d_in[6];
    const float* pw_w = (const float*)d_in[7];
    const float* pw_b = (const float*)d_in[8];
    const float* g2   = (const float*)d_in[9];
    const float* b2   = (const float*)d_in[10];
    const float* m2   = (const float*)d_in[11];
    const float* v2   = (const float*)d_in[12];
    float* out = (float*)d_out;

    dw_kernel<<<64 * 128, 256>>>(x, dw_w, dw_b, g1, b1, m1, v1);
    compact_kernel<<<64, 128>>>();
    pw_kernel<<<dim3(8, 64), 256>>>(pw_w, pw_b, g2, b2, m2, v2, out);
}